// round 2
// baseline (speedup 1.0000x reference)
#include <cuda_runtime.h>
#include <math_constants.h>
#include <stdint.h>

// ---------------------------------------------------------------------------
// TopLoss: loss = t01 + t0 + t1 + t2
//   len_k[i] = dgm_k[i,0] - dgm_k[i,1]   (non-finite -> 0)
//   m  = max(len_0)
//   t01 = 1 - m^2
//   t0  = sum(len_0^2) - m^2      (sum over sorted[1:] == total - max^2)
//   t1  = sum(len_1^2)
//   t2  = sum(len_2^2)
// Output: [loss, t01, t0, t1, t2] as float32.
//
// Streaming HBM-bound: 192 MB read once. Two-kernel deterministic reduction
// (block partials -> __device__ scratch -> single-block finalize in double).
// ---------------------------------------------------------------------------

#define NB 1184            // blocks in pass 1 (148 SMs * 8 resident blocks)
#define NT 256             // threads per block in pass 1

// scratch: per-block partials {s0, s1, s2, max0}
__device__ float g_part[NB * 4];

__device__ __forceinline__ float sanitized_len(float a, float b) {
    float l = a - b;
    return isfinite(l) ? l : 0.0f;
}

__device__ __forceinline__ float warp_sum(float v) {
#pragma unroll
    for (int o = 16; o > 0; o >>= 1) v += __shfl_down_sync(0xFFFFFFFFu, v, o);
    return v;
}
__device__ __forceinline__ float warp_max(float v) {
#pragma unroll
    for (int o = 16; o > 0; o >>= 1) v = fmaxf(v, __shfl_down_sync(0xFFFFFFFFu, v, o));
    return v;
}

__global__ __launch_bounds__(NT) void pass1_kernel(
    const float4* __restrict__ d0,
    const float4* __restrict__ d1,
    const float4* __restrict__ d2,
    long n4,            // number of float4 elements per array
    long n_floats)      // total floats per array (for scalar tail)
{
    float s0 = 0.0f, s1 = 0.0f, s2 = 0.0f;
    float m0 = -CUDART_INF_F;

    const long stride = (long)gridDim.x * blockDim.x;
    for (long i = (long)blockIdx.x * blockDim.x + threadIdx.x; i < n4; i += stride) {
        // three independent 16B load streams -> MLP >= 3 before any use
        float4 a = d0[i];
        float4 b = d1[i];
        float4 c = d2[i];

        float la = sanitized_len(a.x, a.y);
        float lb = sanitized_len(a.z, a.w);
        s0 += la * la + lb * lb;
        m0 = fmaxf(m0, fmaxf(la, lb));

        la = sanitized_len(b.x, b.y);
        lb = sanitized_len(b.z, b.w);
        s1 += la * la + lb * lb;

        la = sanitized_len(c.x, c.y);
        lb = sanitized_len(c.z, c.w);
        s2 += la * la + lb * lb;
    }

    // scalar tail (full pairs beyond n4*4 floats) — one thread; n=16M means none
    if (blockIdx.x == 0 && threadIdx.x == 0) {
        const float* f0 = (const float*)d0;
        const float* f1 = (const float*)d1;
        const float* f2 = (const float*)d2;
        for (long j = n4 * 4; j + 1 < n_floats; j += 2) {
            float l0 = sanitized_len(f0[j], f0[j + 1]);
            s0 += l0 * l0;
            m0 = fmaxf(m0, l0);
            float l1 = sanitized_len(f1[j], f1[j + 1]);
            s1 += l1 * l1;
            float l2 = sanitized_len(f2[j], f2[j + 1]);
            s2 += l2 * l2;
        }
    }

    // block reduction
    __shared__ float sh[4][NT / 32];
    s0 = warp_sum(s0);
    s1 = warp_sum(s1);
    s2 = warp_sum(s2);
    m0 = warp_max(m0);
    int lane = threadIdx.x & 31;
    int wid  = threadIdx.x >> 5;
    if (lane == 0) {
        sh[0][wid] = s0;
        sh[1][wid] = s1;
        sh[2][wid] = s2;
        sh[3][wid] = m0;
    }
    __syncthreads();
    if (wid == 0) {
        const int nw = NT / 32;
        float v0 = (lane < nw) ? sh[0][lane] : 0.0f;
        float v1 = (lane < nw) ? sh[1][lane] : 0.0f;
        float v2 = (lane < nw) ? sh[2][lane] : 0.0f;
        float vm = (lane < nw) ? sh[3][lane] : -CUDART_INF_F;
        v0 = warp_sum(v0);
        v1 = warp_sum(v1);
        v2 = warp_sum(v2);
        vm = warp_max(vm);
        if (lane == 0) {
            g_part[blockIdx.x * 4 + 0] = v0;
            g_part[blockIdx.x * 4 + 1] = v1;
            g_part[blockIdx.x * 4 + 2] = v2;
            g_part[blockIdx.x * 4 + 3] = vm;
        }
    }
}

// one block of 1024 threads reduces the NB partials (double accumulation).
// NB may exceed 1024, so each thread strides over the partial array.
__global__ __launch_bounds__(1024) void pass2_kernel(float* __restrict__ out) {
    __shared__ double shs[3][32];
    __shared__ float  shm[32];

    int t = threadIdx.x;
    double s0 = 0.0, s1 = 0.0, s2 = 0.0;
    float  m0 = -CUDART_INF_F;
    for (int i = t; i < NB; i += 1024) {
        s0 += (double)g_part[i * 4 + 0];
        s1 += (double)g_part[i * 4 + 1];
        s2 += (double)g_part[i * 4 + 2];
        m0 = fmaxf(m0, g_part[i * 4 + 3]);
    }

#pragma unroll
    for (int o = 16; o > 0; o >>= 1) {
        s0 += __shfl_down_sync(0xFFFFFFFFu, s0, o);
        s1 += __shfl_down_sync(0xFFFFFFFFu, s1, o);
        s2 += __shfl_down_sync(0xFFFFFFFFu, s2, o);
        m0 = fmaxf(m0, __shfl_down_sync(0xFFFFFFFFu, m0, o));
    }
    int lane = t & 31, wid = t >> 5;
    if (lane == 0) {
        shs[0][wid] = s0;
        shs[1][wid] = s1;
        shs[2][wid] = s2;
        shm[wid]    = m0;
    }
    __syncthreads();
    if (wid == 0) {
        double v0 = shs[0][lane];
        double v1 = shs[1][lane];
        double v2 = shs[2][lane];
        float  vm = shm[lane];
#pragma unroll
        for (int o = 16; o > 0; o >>= 1) {
            v0 += __shfl_down_sync(0xFFFFFFFFu, v0, o);
            v1 += __shfl_down_sync(0xFFFFFFFFu, v1, o);
            v2 += __shfl_down_sync(0xFFFFFFFFu, v2, o);
            vm = fmaxf(vm, __shfl_down_sync(0xFFFFFFFFu, vm, o));
        }
        if (lane == 0) {
            double m2  = (double)vm * (double)vm;
            double t01 = 1.0 - m2;
            double t0  = v0 - m2;
            double t1  = v1;
            double t2  = v2;
            double loss = t01 + t0 + t1 + t2;
            out[0] = (float)loss;
            out[1] = (float)t01;
            out[2] = (float)t0;
            out[3] = (float)t1;
            out[4] = (float)t2;
        }
    }
}

extern "C" void kernel_launch(void* const* d_in, const int* in_sizes, int n_in,
                              void* d_out, int out_size) {
    const float* d0 = (const float*)d_in[0];
    const float* d1 = (const float*)d_in[1];
    const float* d2 = (const float*)d_in[2];
    float* out = (float*)d_out;

    long n_floats = (long)in_sizes[0];  // 2 * N_BARS = 16M
    long n4 = n_floats / 4;

    pass1_kernel<<<NB, NT>>>((const float4*)d0, (const float4*)d1,
                             (const float4*)d2, n4, n_floats);
    pass2_kernel<<<1, 1024>>>(out);
}